// round 14
// baseline (speedup 1.0000x reference)
#include <cuda_runtime.h>
#include <cuda_fp16.h>
#include <math.h>
#include <float.h>
#include <stdint.h>

#define T_TOKENS 16384
#define HDIM     2048
#define NEXP     256
#define TOPK     8
#define TOPKG    4

#define TAU_E 1e-5f
#define TAU_G 2e-5f
#define FTOK  8          // fixup tokens per CTA batch

// ---------------- static device scratch ----------------
__device__ float g_scores[(size_t)T_TOKENS * NEXP];         // 16 MB
// B fragments, stage-contiguous: [ks(64)][nt(32)][kt2(2)][64 u32]
__device__ __align__(16) uint32_t g_Bh1[64 * 32 * 2 * 64];  // 1 MB
__device__ __align__(16) uint32_t g_Bh2[64 * 32 * 2 * 64];  // 1 MB
__device__ int   g_nflag;
__device__ int   g_flaglist[T_TOKENS];

// ---------------- helpers ----------------
__device__ __forceinline__ uint32_t smem_u32(const void* p) {
    uint32_t a;
    asm("{ .reg .u64 t; cvta.to.shared.u64 t, %1; cvt.u32.u64 %0, t; }" : "=r"(a) : "l"(p));
    return a;
}
__device__ __forceinline__ uint32_t pack_h2(__half lo, __half hi) {
    return (uint32_t)__half_as_ushort(lo) | ((uint32_t)__half_as_ushort(hi) << 16);
}
__device__ __forceinline__ void split2(float p, float q, uint32_t& hi, uint32_t& lo) {
    __half hp = __float2half_rn(p);
    __half hq = __float2half_rn(q);
    __half rp = __float2half_rn(p - __half2float(hp));
    __half rq = __float2half_rn(q - __half2float(hq));
    hi = pack_h2(hp, hq);
    lo = pack_h2(rp, rq);
}
#define MBAR_INIT(a, n) \
    asm volatile("mbarrier.init.shared.b64 [%0], %1;" :: "r"(a), "r"((uint32_t)(n)) : "memory")
#define MBAR_EXPECT_TX(a, b) \
    asm volatile("mbarrier.arrive.expect_tx.shared.b64 _, [%0], %1;" :: "r"(a), "r"((uint32_t)(b)) : "memory")
#define MBAR_WAIT(a, ph) do {                                                   \
    uint32_t _m = (a); uint32_t _p = (ph); uint32_t _d;                         \
    asm volatile("{\n .reg .pred p;\n"                                          \
        " mbarrier.try_wait.parity.acquire.cta.shared::cta.b64 p, [%1], %2;\n"  \
        " selp.b32 %0, 1, 0, p;\n}" : "=r"(_d) : "r"(_m), "r"(_p) : "memory");  \
    if (!_d) {                                                                  \
        asm volatile("{\n .reg .pred P1;\n"                                     \
            "W_%=:\n"                                                           \
            " mbarrier.try_wait.parity.acquire.cta.shared::cta.b64 P1, [%0], %1, 0x989680;\n" \
            " @P1 bra.uni D_%=;\n bra.uni W_%=;\n"                              \
            "D_%=:\n}" :: "r"(_m), "r"(_p) : "memory");                         \
    } } while (0)

__device__ __forceinline__ void bulk_g2s(uint32_t dst, const void* src, uint32_t bytes, uint32_t mbar) {
    asm volatile(
        "cp.async.bulk.shared::cluster.global.mbarrier::complete_tx::bytes [%0], [%1], %2, [%3];"
        :: "r"(dst), "l"(src), "r"(bytes), "r"(mbar) : "memory");
}
__device__ __forceinline__ void mma_f16(float& c0, float& c1, float& c2, float& c3,
                                        uint32_t a0, uint32_t a1, uint32_t a2, uint32_t a3,
                                        uint32_t b0, uint32_t b1) {
    asm volatile(
        "mma.sync.aligned.m16n8k16.row.col.f32.f16.f16.f32 "
        "{%0,%1,%2,%3}, {%4,%5,%6,%7}, {%8,%9}, {%0,%1,%2,%3};"
        : "+f"(c0), "+f"(c1), "+f"(c2), "+f"(c3)
        : "r"(a0), "r"(a1), "r"(a2), "r"(a3), "r"(b0), "r"(b1));
}
#define LDS128(r0, r1, r2, r3, a) \
    asm volatile("ld.shared.v4.b32 {%0,%1,%2,%3}, [%4];" : "=r"(r0), "=r"(r1), "=r"(r2), "=r"(r3) : "r"(a))
#define LDS64(r0, r1, a) \
    asm volatile("ld.shared.v2.b32 {%0,%1}, [%2];" : "=r"(r0), "=r"(r1) : "r"(a))
#define STS128(a, r0, r1, r2, r3) \
    asm volatile("st.shared.v4.b32 [%0], {%1,%2,%3,%4};" :: "r"(a), "r"(r0), "r"(r1), "r"(r2), "r"(r3) : "memory")

// ---------------------------------------------------------------------------
// Routing core (warp-wide), identical semantics to validated R1/R4/R6/R7/R9.
// ---------------------------------------------------------------------------
__device__ __forceinline__ void route_core(const float s[8], const float ch[8],
                                           int lane, int t, float* out,
                                           bool do_margin, float* margin_e, float* margin_g)
{
    const unsigned FULL = 0xffffffffu;
    float m1 = -FLT_MAX, m2 = -FLT_MAX;
    #pragma unroll
    for (int j = 0; j < 8; j++) {
        float v = ch[j];
        if (v > m1) { m2 = m1; m1 = v; }
        else if (v > m2) { m2 = v; }
    }
    #pragma unroll
    for (int off = 1; off < 4; off <<= 1) {
        float om1 = __shfl_xor_sync(FULL, m1, off);
        float om2 = __shfl_xor_sync(FULL, m2, off);
        if (om1 > m1) { m2 = fmaxf(m1, om2); m1 = om1; }
        else          { m2 = fmaxf(m2, om1); }
    }
    float gs = m1 + m2;
    float gsv[8];
    #pragma unroll
    for (int gg = 0; gg < 8; gg++) gsv[gg] = __shfl_sync(FULL, gs, gg * 4);

    unsigned gmask = 0;
    float bv4 = -FLT_MAX;
    #pragma unroll
    for (int r = 0; r < TOPKG; r++) {
        float bv = -FLT_MAX; int bi = 0;
        #pragma unroll
        for (int gg = 0; gg < 8; gg++) {
            bool used = (gmask >> gg) & 1u;
            if (!used && gsv[gg] > bv) { bv = gsv[gg]; bi = gg; }
        }
        gmask |= (1u << bi);
        bv4 = bv;
    }
    if (do_margin) {
        float g5 = -FLT_MAX;
        #pragma unroll
        for (int gg = 0; gg < 8; gg++)
            if (!((gmask >> gg) & 1u) && gsv[gg] > g5) g5 = gsv[gg];
        *margin_g = bv4 - g5;
    }

    float tmp[8];
    bool gon = (gmask >> (lane >> 2)) & 1u;
    #pragma unroll
    for (int j = 0; j < 8; j++) tmp[j] = gon ? ch[j] : 0.0f;

    int   idxs[TOPK];
    float wts[TOPK];
    float wsum = 0.0f;
    float prevv = FLT_MAX, mgap = FLT_MAX;
    const int NROUND = 9;
    #pragma unroll
    for (int r = 0; r < NROUND; r++) {
        float bv = -FLT_MAX; int bj = 0;
        #pragma unroll
        for (int j = 0; j < 8; j++)
            if (tmp[j] > bv) { bv = tmp[j]; bj = j; }
        int gi = lane * 8 + bj;
        #pragma unroll
        for (int off = 16; off > 0; off >>= 1) {
            float ov = __shfl_xor_sync(FULL, bv, off);
            int   oi = __shfl_xor_sync(FULL, gi, off);
            if (ov > bv || (ov == bv && oi < gi)) { bv = ov; gi = oi; }
        }
        if (r > 0) mgap = fminf(mgap, prevv - bv);
        prevv = bv;
        if (r < TOPK) {
            float myw = s[gi & 7];
            float wv = __shfl_sync(FULL, myw, gi >> 3);
            if ((gi >> 3) == lane) tmp[gi & 7] = -FLT_MAX;
            idxs[r] = gi;
            wts[r]  = wv;
            wsum   += wv;
        }
        if (!do_margin && r == TOPK - 1) break;
    }
    if (do_margin) *margin_e = mgap;

    if (lane == 0) {
        float denom = wsum + 1e-20f;
        #pragma unroll
        for (int r = 0; r < TOPK; r++) {
            out[(size_t)t * TOPK + r] = (float)idxs[r];
            out[(size_t)T_TOKENS * TOPK + (size_t)t * TOPK + r] =
                (wts[r] / denom) * 2.5f;
        }
    }
}

// ---------------------------------------------------------------------------
// split_b: w -> fp16 hi/lo B fragments, stage-contiguous.
// ---------------------------------------------------------------------------
__global__ __launch_bounds__(256) void split_b_kernel(const float* __restrict__ w) {
    if (blockIdx.x == 0 && threadIdx.x == 0) g_nflag = 0;
    int tile = blockIdx.x * 8 + (threadIdx.x >> 5);   // nt*128 + kt
    int lane = threadIdx.x & 31;
    int nt = tile >> 7;
    int kt = tile & 127;
    int ks = kt >> 1, kt2 = kt & 1;
    int g = lane >> 2, t = lane & 3;
    const float* base = w + (size_t)(nt * 8 + g) * HDIM + kt * 16;
    float2 u0 = *(const float2*)(base + 2 * t);
    float2 u1 = *(const float2*)(base + 2 * t + 8);
    uint32_t b0h, b0l, b1h, b1l;
    split2(u0.x, u0.y, b0h, b0l);
    split2(u1.x, u1.y, b1h, b1l);
    size_t o = (size_t)(((ks * 32 + nt) * 2 + kt2)) * 64 + lane * 2;
    g_Bh1[o] = b0h; g_Bh1[o + 1] = b1h;
    g_Bh2[o] = b0l; g_Bh2[o + 1] = b1l;
}

// ---------------------------------------------------------------------------
// GEMM: fused A-split (LDG->split->STS) + 3x fp16 mma.sync, BM=128 BN=256.
// ---------------------------------------------------------------------------
#define BSTAGES  4
#define OFF_B    32768
#define B_STG_SZ 32768
#define OFF_MBAR (OFF_B + BSTAGES * B_STG_SZ)    // 163840
#define SMEM_SZ  (OFF_MBAR + 64)
#define NITER    (HDIM / 32)   // 64

__device__ __forceinline__ void issue_b(uint32_t sb, int s, int ks) {
    uint32_t stg = sb + OFF_B + s * B_STG_SZ;
    uint32_t mb  = sb + OFF_MBAR + s * 8;
    MBAR_EXPECT_TX(mb, B_STG_SZ);
    bulk_g2s(stg,         g_Bh1 + (size_t)ks * 4096, 16384, mb);
    bulk_g2s(stg + 16384, g_Bh2 + (size_t)ks * 4096, 16384, mb);
}

__device__ __forceinline__ void lda(const float* __restrict__ x, int bm, int ks,
                                    int wid, int g, int t, float2 pr[8]) {
    #pragma unroll
    for (int b = 0; b < 2; b++) {
        int bi = wid * 2 + b;
        int mt = bi >> 1, kt2 = bi & 1;
        const float* p = x + (size_t)(bm + mt * 16 + g) * HDIM + ks * 32 + kt2 * 16 + 2 * t;
        pr[b * 4 + 0] = *(const float2*)(p);
        pr[b * 4 + 1] = *(const float2*)(p + 8 * HDIM);
        pr[b * 4 + 2] = *(const float2*)(p + 8);
        pr[b * 4 + 3] = *(const float2*)(p + 8 * HDIM + 8);
    }
}
__device__ __forceinline__ void sts_a(uint32_t abuf, int wid, int lane, const float2 pr[8]) {
    #pragma unroll
    for (int b = 0; b < 2; b++) {
        int bi = wid * 2 + b;
        uint32_t h[4], l[4];
        #pragma unroll
        for (int j = 0; j < 4; j++)
            split2(pr[b * 4 + j].x, pr[b * 4 + j].y, h[j], l[j]);
        uint32_t dst = abuf + (uint32_t)bi * 512 + lane * 16;
        STS128(dst,        h[0], h[1], h[2], h[3]);
        STS128(dst + 8192, l[0], l[1], l[2], l[3]);
    }
}

__global__ __launch_bounds__(256, 1) void gemm_mma_kernel(const float* __restrict__ x) {
    extern __shared__ __align__(1024) char smem[];
    const uint32_t sb = smem_u32(smem);
    const int tid  = threadIdx.x;
    const int wid  = tid >> 5;
    const int lane = tid & 31;
    const int g    = lane >> 2, t = lane & 3;
    const int wm   = wid >> 2;
    const int wn   = wid & 3;
    const int bm   = blockIdx.x * 128;

    if (tid == 0) {
        #pragma unroll
        for (int s = 0; s < BSTAGES; s++) MBAR_INIT(sb + OFF_MBAR + s * 8, 1);
    }
    __syncthreads();
    if (tid == 0) {
        #pragma unroll
        for (int s = 0; s < BSTAGES; s++) issue_b(sb, s, s);
    }

    float2 pr[8];
    lda(x, bm, 0, wid, g, t, pr);
    sts_a(sb, wid, lane, pr);
    __syncthreads();

    float acc[4][8][4];
    #pragma unroll
    for (int i = 0; i < 4; i++)
        #pragma unroll
        for (int j = 0; j < 8; j++)
            #pragma unroll
            for (int q = 0; q < 4; q++) acc[i][j][q] = 0.0f;

    int ph[BSTAGES] = {0, 0, 0, 0};

    for (int it = 0; it < NITER; it++) {
        const int sB = it & (BSTAGES - 1);
        const uint32_t stgA = sb + (uint32_t)(it & 1) * 16384;
        const uint32_t stgB = sb + OFF_B + sB * B_STG_SZ;

        if (it + 1 < NITER) lda(x, bm, it + 1, wid, g, t, pr);

        MBAR_WAIT(sb + OFF_MBAR + sB * 8, ph[sB]);
        ph[sB] ^= 1;

        #pragma unroll
        for (int kt2 = 0; kt2 < 2; kt2++) {
            uint32_t ah[4][4], al[4][4], bh[8][2], bl[8][2];
            #pragma unroll
            for (int mi = 0; mi < 4; mi++) {
                uint32_t off = (uint32_t)(((wm * 4 + mi) * 2 + kt2) * 512 + lane * 16);
                LDS128(ah[mi][0], ah[mi][1], ah[mi][2], ah[mi][3], stgA + off);
                LDS128(al[mi][0], al[mi][1], al[mi][2], al[mi][3], stgA + 8192 + off);
            }
            #pragma unroll
            for (int ni = 0; ni < 8; ni++) {
                uint32_t off = (uint32_t)(((wn * 8 + ni) * 2 + kt2) * 256 + lane * 8);
                LDS64(bh[ni][0], bh[ni][1], stgB + off);
                LDS64(bl[ni][0], bl[ni][1], stgB + 16384 + off);
            }
            #pragma unroll
            for (int mi = 0; mi < 4; mi++)
                #pragma unroll
                for (int ni = 0; ni < 8; ni++) {
                    float* c = acc[mi][ni];
                    mma_f16(c[0], c[1], c[2], c[3],
                            ah[mi][0], ah[mi][1], ah[mi][2], ah[mi][3],
                            bh[ni][0], bh[ni][1]);
                    mma_f16(c[0], c[1], c[2], c[3],
                            ah[mi][0], ah[mi][1], ah[mi][2], ah[mi][3],
                            bl[ni][0], bl[ni][1]);
                    mma_f16(c[0], c[1], c[2], c[3],
                            al[mi][0], al[mi][1], al[mi][2], al[mi][3],
                            bh[ni][0], bh[ni][1]);
                }
        }

        if (it + 1 < NITER)
            sts_a(sb + (uint32_t)((it + 1) & 1) * 16384, wid, lane, pr);
        __syncthreads();
        if (tid == 0 && it + BSTAGES < NITER)
            issue_b(sb, sB, it + BSTAGES);
    }

    // epilogue: sigmoid -> g_scores
    #pragma unroll
    for (int mi = 0; mi < 4; mi++) {
        int r0 = bm + (wm * 4 + mi) * 16 + g;
        #pragma unroll
        for (int ni = 0; ni < 8; ni++) {
            int cc = (wn * 8 + ni) * 8 + t * 2;
            float* c = acc[mi][ni];
            float2 lo = make_float2(1.0f / (1.0f + expf(-c[0])),
                                    1.0f / (1.0f + expf(-c[1])));
            float2 hi = make_float2(1.0f / (1.0f + expf(-c[2])),
                                    1.0f / (1.0f + expf(-c[3])));
            *(float2*)(g_scores + (size_t)r0 * NEXP + cc) = lo;
            *(float2*)(g_scores + (size_t)(r0 + 8) * NEXP + cc) = hi;
        }
    }
}

// ---------------------------------------------------------------------------
// Routing kernel: one warp per token (deep occupancy hides shfl latency).
// ---------------------------------------------------------------------------
__global__ __launch_bounds__(256) void route_kernel(
    const float* __restrict__ bias, float* __restrict__ out)
{
    const int warp = threadIdx.x >> 5;
    const int lane = threadIdx.x & 31;
    const int t = blockIdx.x * 8 + warp;

    const float* sp = g_scores + (size_t)t * NEXP + lane * 8;
    float s[8], ch[8];
    float4 v0 = *(const float4*)(sp);
    float4 v1 = *(const float4*)(sp + 4);
    s[0]=v0.x; s[1]=v0.y; s[2]=v0.z; s[3]=v0.w;
    s[4]=v1.x; s[5]=v1.y; s[6]=v1.z; s[7]=v1.w;
    const float* bp = bias + lane * 8;
    float4 b0 = *(const float4*)(bp);
    float4 b1 = *(const float4*)(bp + 4);
    ch[0]=s[0]+b0.x; ch[1]=s[1]+b0.y; ch[2]=s[2]+b0.z; ch[3]=s[3]+b0.w;
    ch[4]=s[4]+b1.x; ch[5]=s[5]+b1.y; ch[6]=s[6]+b1.z; ch[7]=s[7]+b1.w;

    float me, mg;
    route_core(s, ch, lane, t, out, true, &me, &mg);

    if (lane == 0 && (me < TAU_E || mg < TAU_G)) {
        int p = atomicAdd(&g_nflag, 1);
        g_flaglist[p] = t;
    }
}

// ---------------------------------------------------------------------------
// Fixup: barrier-free chunk loop, FTOK=8 tokens/batch. Thread tid owns expert
// row tid; w streamed per-thread via register double-buffered LDG.128 (no smem
// staging, no syncs in the k-loop). Doubled per-chunk compute (512 FMA) now
// covers the w-LDG latency; halved batch count -> one wave; halved chip-wide
// w traffic. x tokens staged in dynamic smem, broadcast-read. Per-expert FFMA
// chain: single accumulator, strictly ascending k — bitwise identical to the
// validated R7-R13 fixup.
// dyn smem: xs[8][2048] (64K) | sc[8][256] (8K) = 73728 B
// ---------------------------------------------------------------------------
#define FIX_SMEM ((FTOK * HDIM + FTOK * NEXP) * 4)

__global__ __launch_bounds__(256) void fixup_kernel(
    const float* __restrict__ x, const float* __restrict__ w,
    const float* __restrict__ bias, float* __restrict__ out)
{
    extern __shared__ float fsm[];
    float* xs = fsm;                 // FTOK*HDIM
    float* sc = fsm + FTOK * HDIM;   // FTOK*NEXP
    const int tid = threadIdx.x;
    const int nf = g_nflag;

    for (int base = blockIdx.x * FTOK; base < nf; base += gridDim.x * FTOK) {
        const int ntk = (nf - base < FTOK) ? (nf - base) : FTOK;
        __syncthreads();   // protect xs/sc reuse across batches

        // stage x tokens into smem (float4, coalesced)
        #pragma unroll
        for (int j = 0; j < FTOK; j++) {
            int tt = g_flaglist[base + (j < ntk ? j : 0)];
            const float4* src = (const float4*)(x + (size_t)tt * HDIM);
            #pragma unroll
            for (int i = 0; i < HDIM / 4 / 256; i++)
                ((float4*)xs)[j * (HDIM / 4) + tid + i * 256] = src[tid + i * 256];
        }
        __syncthreads();

        const float4* wrow = (const float4*)(w + (size_t)tid * HDIM);
        float4 cur[8], nxt[8];
        #pragma unroll
        for (int i = 0; i < 8; i++) cur[i] = wrow[i];

        float acc[FTOK];
        #pragma unroll
        for (int j = 0; j < FTOK; j++) acc[j] = 0.0f;

        for (int kc = 0; kc < 64; kc++) {
            if (kc + 1 < 64) {
                #pragma unroll
                for (int i = 0; i < 8; i++)
                    nxt[i] = wrow[(kc + 1) * 8 + i];
            }
            #pragma unroll
            for (int i = 0; i < 8; i++) {
                float4 wv = cur[i];
                #pragma unroll
                for (int j = 0; j < FTOK; j++) {
                    const float4 xv = *(const float4*)(xs + j * HDIM + kc * 32 + i * 4);
                    float a = acc[j];
                    a = fmaf(xv.x, wv.x, a);
                    a = fmaf(xv.y, wv.y, a);
                    a = fmaf(xv.z, wv.z, a);
                    a = fmaf(xv.w, wv.w, a);
                    acc[j] = a;
                }
            }
            #pragma unroll
            for (int i = 0; i < 8; i++) cur[i] = nxt[i];
        }

        #pragma unroll
        for (int j = 0; j < FTOK; j++)
            sc[j * NEXP + tid] = 1.0f / (1.0f + expf(-acc[j]));
        __syncthreads();

        const int wid = tid >> 5, lane = tid & 31;
        if (wid < ntk) {
            int tt = g_flaglist[base + wid];
            float s[8], ch[8];
            #pragma unroll
            for (int j = 0; j < 8; j++) {
                s[j]  = sc[wid * NEXP + lane * 8 + j];
                ch[j] = s[j] + bias[lane * 8 + j];
            }
            float me, mg;
            route_core(s, ch, lane, tt, out, false, &me, &mg);
        }
    }
}

// ---------------------------------------------------------------------------
extern "C" void kernel_launch(void* const* d_in, const int* in_sizes, int n_in,
                              void* d_out, int out_size)
{
    const float* x    = (const float*)d_in[0];   // [4,4096,2048]
    const float* w    = (const float*)d_in[1];   // [256,2048]
    const float* bias = (const float*)d_in[2];   // [256]
    float* out = (float*)d_out;

    cudaFuncSetAttribute(gemm_mma_kernel,
                         cudaFuncAttributeMaxDynamicSharedMemorySize, SMEM_SZ);
    cudaFuncSetAttribute(fixup_kernel,
                         cudaFuncAttributeMaxDynamicSharedMemorySize, FIX_SMEM);

    split_b_kernel<<<(NEXP / 8) * (HDIM / 16) / 8, 256>>>(w);
    gemm_mma_kernel<<<T_TOKENS / 128, 256, SMEM_SZ>>>(x);
    route_kernel<<<T_TOKENS / 8, 256>>>(bias, out);
    fixup_kernel<<<512, 256, FIX_SMEM>>>(x, w, bias, out);
}

// round 17
// speedup vs baseline: 1.1761x; 1.1761x over previous
#include <cuda_runtime.h>
#include <cuda_fp16.h>
#include <math.h>
#include <float.h>
#include <stdint.h>

#define T_TOKENS 16384
#define HDIM     2048
#define NEXP     256
#define TOPK     8
#define TOPKG    4

#define TAU_E 1e-5f
#define TAU_G 2e-5f

// ---------------- static device scratch ----------------
__device__ float g_scores[(size_t)T_TOKENS * NEXP];         // 16 MB
// B fragments, stage-contiguous: [ks(64)][nt(32)][kt2(2)][64 u32]
__device__ __align__(16) uint32_t g_Bh1[64 * 32 * 2 * 64];  // 1 MB
__device__ __align__(16) uint32_t g_Bh2[64 * 32 * 2 * 64];  // 1 MB
__device__ int   g_nflag;
__device__ int   g_flaglist[T_TOKENS];

// ---------------- helpers ----------------
__device__ __forceinline__ uint32_t smem_u32(const void* p) {
    uint32_t a;
    asm("{ .reg .u64 t; cvta.to.shared.u64 t, %1; cvt.u32.u64 %0, t; }" : "=r"(a) : "l"(p));
    return a;
}
__device__ __forceinline__ uint32_t pack_h2(__half lo, __half hi) {
    return (uint32_t)__half_as_ushort(lo) | ((uint32_t)__half_as_ushort(hi) << 16);
}
__device__ __forceinline__ void split2(float p, float q, uint32_t& hi, uint32_t& lo) {
    __half hp = __float2half_rn(p);
    __half hq = __float2half_rn(q);
    __half rp = __float2half_rn(p - __half2float(hp));
    __half rq = __float2half_rn(q - __half2float(hq));
    hi = pack_h2(hp, hq);
    lo = pack_h2(rp, rq);
}
#define MBAR_INIT(a, n) \
    asm volatile("mbarrier.init.shared.b64 [%0], %1;" :: "r"(a), "r"((uint32_t)(n)) : "memory")
#define MBAR_EXPECT_TX(a, b) \
    asm volatile("mbarrier.arrive.expect_tx.shared.b64 _, [%0], %1;" :: "r"(a), "r"((uint32_t)(b)) : "memory")
#define MBAR_WAIT(a, ph) do {                                                   \
    uint32_t _m = (a); uint32_t _p = (ph); uint32_t _d;                         \
    asm volatile("{\n .reg .pred p;\n"                                          \
        " mbarrier.try_wait.parity.acquire.cta.shared::cta.b64 p, [%1], %2;\n"  \
        " selp.b32 %0, 1, 0, p;\n}" : "=r"(_d) : "r"(_m), "r"(_p) : "memory");  \
    if (!_d) {                                                                  \
        asm volatile("{\n .reg .pred P1;\n"                                     \
            "W_%=:\n"                                                           \
            " mbarrier.try_wait.parity.acquire.cta.shared::cta.b64 P1, [%0], %1, 0x989680;\n" \
            " @P1 bra.uni D_%=;\n bra.uni W_%=;\n"                              \
            "D_%=:\n}" :: "r"(_m), "r"(_p) : "memory");                         \
    } } while (0)

__device__ __forceinline__ void bulk_g2s(uint32_t dst, const void* src, uint32_t bytes, uint32_t mbar) {
    asm volatile(
        "cp.async.bulk.shared::cluster.global.mbarrier::complete_tx::bytes [%0], [%1], %2, [%3];"
        :: "r"(dst), "l"(src), "r"(bytes), "r"(mbar) : "memory");
}
#define CP_ASYNC16(sa, gp) \
    asm volatile("cp.async.ca.shared.global [%0], [%1], 16;" :: "r"(sa), "l"(gp) : "memory")
#define CP_COMMIT() asm volatile("cp.async.commit_group;" ::: "memory")
#define CP_WAIT(n)  asm volatile("cp.async.wait_group %0;" :: "n"(n) : "memory")

__device__ __forceinline__ void mma_f16(float& c0, float& c1, float& c2, float& c3,
                                        uint32_t a0, uint32_t a1, uint32_t a2, uint32_t a3,
                                        uint32_t b0, uint32_t b1) {
    asm volatile(
        "mma.sync.aligned.m16n8k16.row.col.f32.f16.f16.f32 "
        "{%0,%1,%2,%3}, {%4,%5,%6,%7}, {%8,%9}, {%0,%1,%2,%3};"
        : "+f"(c0), "+f"(c1), "+f"(c2), "+f"(c3)
        : "r"(a0), "r"(a1), "r"(a2), "r"(a3), "r"(b0), "r"(b1));
}
#define LDS128(r0, r1, r2, r3, a) \
    asm volatile("ld.shared.v4.b32 {%0,%1,%2,%3}, [%4];" : "=r"(r0), "=r"(r1), "=r"(r2), "=r"(r3) : "r"(a))
#define LDS64(r0, r1, a) \
    asm volatile("ld.shared.v2.b32 {%0,%1}, [%2];" : "=r"(r0), "=r"(r1) : "r"(a))
#define STS128(a, r0, r1, r2, r3) \
    asm volatile("st.shared.v4.b32 [%0], {%1,%2,%3,%4};" :: "r"(a), "r"(r0), "r"(r1), "r"(r2), "r"(r3) : "memory")

// ---------------------------------------------------------------------------
// Routing core (warp-wide), identical semantics to validated R1/R4/R6/R7/R9.
// ---------------------------------------------------------------------------
__device__ __forceinline__ void route_core(const float s[8], const float ch[8],
                                           int lane, int t, float* out,
                                           bool do_margin, float* margin_e, float* margin_g)
{
    const unsigned FULL = 0xffffffffu;
    float m1 = -FLT_MAX, m2 = -FLT_MAX;
    #pragma unroll
    for (int j = 0; j < 8; j++) {
        float v = ch[j];
        if (v > m1) { m2 = m1; m1 = v; }
        else if (v > m2) { m2 = v; }
    }
    #pragma unroll
    for (int off = 1; off < 4; off <<= 1) {
        float om1 = __shfl_xor_sync(FULL, m1, off);
        float om2 = __shfl_xor_sync(FULL, m2, off);
        if (om1 > m1) { m2 = fmaxf(m1, om2); m1 = om1; }
        else          { m2 = fmaxf(m2, om1); }
    }
    float gs = m1 + m2;
    float gsv[8];
    #pragma unroll
    for (int gg = 0; gg < 8; gg++) gsv[gg] = __shfl_sync(FULL, gs, gg * 4);

    unsigned gmask = 0;
    float bv4 = -FLT_MAX;
    #pragma unroll
    for (int r = 0; r < TOPKG; r++) {
        float bv = -FLT_MAX; int bi = 0;
        #pragma unroll
        for (int gg = 0; gg < 8; gg++) {
            bool used = (gmask >> gg) & 1u;
            if (!used && gsv[gg] > bv) { bv = gsv[gg]; bi = gg; }
        }
        gmask |= (1u << bi);
        bv4 = bv;
    }
    if (do_margin) {
        float g5 = -FLT_MAX;
        #pragma unroll
        for (int gg = 0; gg < 8; gg++)
            if (!((gmask >> gg) & 1u) && gsv[gg] > g5) g5 = gsv[gg];
        *margin_g = bv4 - g5;
    }

    float tmp[8];
    bool gon = (gmask >> (lane >> 2)) & 1u;
    #pragma unroll
    for (int j = 0; j < 8; j++) tmp[j] = gon ? ch[j] : 0.0f;

    int   idxs[TOPK];
    float wts[TOPK];
    float wsum = 0.0f;
    float prevv = FLT_MAX, mgap = FLT_MAX;
    const int NROUND = 9;
    #pragma unroll
    for (int r = 0; r < NROUND; r++) {
        float bv = -FLT_MAX; int bj = 0;
        #pragma unroll
        for (int j = 0; j < 8; j++)
            if (tmp[j] > bv) { bv = tmp[j]; bj = j; }
        int gi = lane * 8 + bj;
        #pragma unroll
        for (int off = 16; off > 0; off >>= 1) {
            float ov = __shfl_xor_sync(FULL, bv, off);
            int   oi = __shfl_xor_sync(FULL, gi, off);
            if (ov > bv || (ov == bv && oi < gi)) { bv = ov; gi = oi; }
        }
        if (r > 0) mgap = fminf(mgap, prevv - bv);
        prevv = bv;
        if (r < TOPK) {
            float myw = s[gi & 7];
            float wv = __shfl_sync(FULL, myw, gi >> 3);
            if ((gi >> 3) == lane) tmp[gi & 7] = -FLT_MAX;
            idxs[r] = gi;
            wts[r]  = wv;
            wsum   += wv;
        }
        if (!do_margin && r == TOPK - 1) break;
    }
    if (do_margin) *margin_e = mgap;

    if (lane == 0) {
        float denom = wsum + 1e-20f;
        #pragma unroll
        for (int r = 0; r < TOPK; r++) {
            out[(size_t)t * TOPK + r] = (float)idxs[r];
            out[(size_t)T_TOKENS * TOPK + (size_t)t * TOPK + r] =
                (wts[r] / denom) * 2.5f;
        }
    }
}

// ---------------------------------------------------------------------------
// split_b: w -> fp16 hi/lo B fragments, stage-contiguous.
// ---------------------------------------------------------------------------
__global__ __launch_bounds__(256) void split_b_kernel(const float* __restrict__ w) {
    if (blockIdx.x == 0 && threadIdx.x == 0) g_nflag = 0;
    int tile = blockIdx.x * 8 + (threadIdx.x >> 5);   // nt*128 + kt
    int lane = threadIdx.x & 31;
    int nt = tile >> 7;
    int kt = tile & 127;
    int ks = kt >> 1, kt2 = kt & 1;
    int g = lane >> 2, t = lane & 3;
    const float* base = w + (size_t)(nt * 8 + g) * HDIM + kt * 16;
    float2 u0 = *(const float2*)(base + 2 * t);
    float2 u1 = *(const float2*)(base + 2 * t + 8);
    uint32_t b0h, b0l, b1h, b1l;
    split2(u0.x, u0.y, b0h, b0l);
    split2(u1.x, u1.y, b1h, b1l);
    size_t o = (size_t)(((ks * 32 + nt) * 2 + kt2)) * 64 + lane * 2;
    g_Bh1[o] = b0h; g_Bh1[o + 1] = b1h;
    g_Bh2[o] = b0l; g_Bh2[o + 1] = b1l;
}

// ---------------------------------------------------------------------------
// GEMM: fused A-split (LDG->split->STS) + 3x fp16 mma.sync, BM=128 BN=256.
// ---------------------------------------------------------------------------
#define BSTAGES  4
#define OFF_B    32768
#define B_STG_SZ 32768
#define OFF_MBAR (OFF_B + BSTAGES * B_STG_SZ)    // 163840
#define SMEM_SZ  (OFF_MBAR + 64)
#define NITER    (HDIM / 32)   // 64

__device__ __forceinline__ void issue_b(uint32_t sb, int s, int ks) {
    uint32_t stg = sb + OFF_B + s * B_STG_SZ;
    uint32_t mb  = sb + OFF_MBAR + s * 8;
    MBAR_EXPECT_TX(mb, B_STG_SZ);
    bulk_g2s(stg,         g_Bh1 + (size_t)ks * 4096, 16384, mb);
    bulk_g2s(stg + 16384, g_Bh2 + (size_t)ks * 4096, 16384, mb);
}

__device__ __forceinline__ void lda(const float* __restrict__ x, int bm, int ks,
                                    int wid, int g, int t, float2 pr[8]) {
    #pragma unroll
    for (int b = 0; b < 2; b++) {
        int bi = wid * 2 + b;
        int mt = bi >> 1, kt2 = bi & 1;
        const float* p = x + (size_t)(bm + mt * 16 + g) * HDIM + ks * 32 + kt2 * 16 + 2 * t;
        pr[b * 4 + 0] = *(const float2*)(p);
        pr[b * 4 + 1] = *(const float2*)(p + 8 * HDIM);
        pr[b * 4 + 2] = *(const float2*)(p + 8);
        pr[b * 4 + 3] = *(const float2*)(p + 8 * HDIM + 8);
    }
}
__device__ __forceinline__ void sts_a(uint32_t abuf, int wid, int lane, const float2 pr[8]) {
    #pragma unroll
    for (int b = 0; b < 2; b++) {
        int bi = wid * 2 + b;
        uint32_t h[4], l[4];
        #pragma unroll
        for (int j = 0; j < 4; j++)
            split2(pr[b * 4 + j].x, pr[b * 4 + j].y, h[j], l[j]);
        uint32_t dst = abuf + (uint32_t)bi * 512 + lane * 16;
        STS128(dst,        h[0], h[1], h[2], h[3]);
        STS128(dst + 8192, l[0], l[1], l[2], l[3]);
    }
}

__global__ __launch_bounds__(256, 1) void gemm_mma_kernel(const float* __restrict__ x) {
    extern __shared__ __align__(1024) char smem[];
    const uint32_t sb = smem_u32(smem);
    const int tid  = threadIdx.x;
    const int wid  = tid >> 5;
    const int lane = tid & 31;
    const int g    = lane >> 2, t = lane & 3;
    const int wm   = wid >> 2;
    const int wn   = wid & 3;
    const int bm   = blockIdx.x * 128;

    if (tid == 0) {
        #pragma unroll
        for (int s = 0; s < BSTAGES; s++) MBAR_INIT(sb + OFF_MBAR + s * 8, 1);
    }
    __syncthreads();
    if (tid == 0) {
        #pragma unroll
        for (int s = 0; s < BSTAGES; s++) issue_b(sb, s, s);
    }

    float2 pr[8];
    lda(x, bm, 0, wid, g, t, pr);
    sts_a(sb, wid, lane, pr);
    __syncthreads();

    float acc[4][8][4];
    #pragma unroll
    for (int i = 0; i < 4; i++)
        #pragma unroll
        for (int j = 0; j < 8; j++)
            #pragma unroll
            for (int q = 0; q < 4; q++) acc[i][j][q] = 0.0f;

    int ph[BSTAGES] = {0, 0, 0, 0};

    for (int it = 0; it < NITER; it++) {
        const int sB = it & (BSTAGES - 1);
        const uint32_t stgA = sb + (uint32_t)(it & 1) * 16384;
        const uint32_t stgB = sb + OFF_B + sB * B_STG_SZ;

        if (it + 1 < NITER) lda(x, bm, it + 1, wid, g, t, pr);

        MBAR_WAIT(sb + OFF_MBAR + sB * 8, ph[sB]);
        ph[sB] ^= 1;

        #pragma unroll
        for (int kt2 = 0; kt2 < 2; kt2++) {
            uint32_t ah[4][4], al[4][4], bh[8][2], bl[8][2];
            #pragma unroll
            for (int mi = 0; mi < 4; mi++) {
                uint32_t off = (uint32_t)(((wm * 4 + mi) * 2 + kt2) * 512 + lane * 16);
                LDS128(ah[mi][0], ah[mi][1], ah[mi][2], ah[mi][3], stgA + off);
                LDS128(al[mi][0], al[mi][1], al[mi][2], al[mi][3], stgA + 8192 + off);
            }
            #pragma unroll
            for (int ni = 0; ni < 8; ni++) {
                uint32_t off = (uint32_t)(((wn * 8 + ni) * 2 + kt2) * 256 + lane * 8);
                LDS64(bh[ni][0], bh[ni][1], stgB + off);
                LDS64(bl[ni][0], bl[ni][1], stgB + 16384 + off);
            }
            #pragma unroll
            for (int mi = 0; mi < 4; mi++)
                #pragma unroll
                for (int ni = 0; ni < 8; ni++) {
                    float* c = acc[mi][ni];
                    mma_f16(c[0], c[1], c[2], c[3],
                            ah[mi][0], ah[mi][1], ah[mi][2], ah[mi][3],
                            bh[ni][0], bh[ni][1]);
                    mma_f16(c[0], c[1], c[2], c[3],
                            ah[mi][0], ah[mi][1], ah[mi][2], ah[mi][3],
                            bl[ni][0], bl[ni][1]);
                    mma_f16(c[0], c[1], c[2], c[3],
                            al[mi][0], al[mi][1], al[mi][2], al[mi][3],
                            bh[ni][0], bh[ni][1]);
                }
        }

        if (it + 1 < NITER)
            sts_a(sb + (uint32_t)((it + 1) & 1) * 16384, wid, lane, pr);
        __syncthreads();
        if (tid == 0 && it + BSTAGES < NITER)
            issue_b(sb, sB, it + BSTAGES);
    }

    // epilogue: sigmoid -> g_scores
    #pragma unroll
    for (int mi = 0; mi < 4; mi++) {
        int r0 = bm + (wm * 4 + mi) * 16 + g;
        #pragma unroll
        for (int ni = 0; ni < 8; ni++) {
            int cc = (wn * 8 + ni) * 8 + t * 2;
            float* c = acc[mi][ni];
            float2 lo = make_float2(1.0f / (1.0f + expf(-c[0])),
                                    1.0f / (1.0f + expf(-c[1])));
            float2 hi = make_float2(1.0f / (1.0f + expf(-c[2])),
                                    1.0f / (1.0f + expf(-c[3])));
            *(float2*)(g_scores + (size_t)r0 * NEXP + cc) = lo;
            *(float2*)(g_scores + (size_t)(r0 + 8) * NEXP + cc) = hi;
        }
    }
}

// ---------------------------------------------------------------------------
// Routing kernel: one warp per token (deep occupancy hides shfl latency).
// ---------------------------------------------------------------------------
__global__ __launch_bounds__(256) void route_kernel(
    const float* __restrict__ bias, float* __restrict__ out)
{
    const int warp = threadIdx.x >> 5;
    const int lane = threadIdx.x & 31;
    const int t = blockIdx.x * 8 + warp;

    const float* sp = g_scores + (size_t)t * NEXP + lane * 8;
    float s[8], ch[8];
    float4 v0 = *(const float4*)(sp);
    float4 v1 = *(const float4*)(sp + 4);
    s[0]=v0.x; s[1]=v0.y; s[2]=v0.z; s[3]=v0.w;
    s[4]=v1.x; s[5]=v1.y; s[6]=v1.z; s[7]=v1.w;
    const float* bp = bias + lane * 8;
    float4 b0 = *(const float4*)(bp);
    float4 b1 = *(const float4*)(bp + 4);
    ch[0]=s[0]+b0.x; ch[1]=s[1]+b0.y; ch[2]=s[2]+b0.z; ch[3]=s[3]+b0.w;
    ch[4]=s[4]+b1.x; ch[5]=s[5]+b1.y; ch[6]=s[6]+b1.z; ch[7]=s[7]+b1.w;

    float me, mg;
    route_core(s, ch, lane, t, out, true, &me, &mg);

    if (lane == 0 && (me < TAU_E || mg < TAU_G)) {
        int p = atomicAdd(&g_nflag, 1);
        g_flaglist[p] = t;
    }
}

// ---------------------------------------------------------------------------
// Fixup: ONE CTA PER FLAGGED TOKEN (grid 2048; CTAs beyond nf exit instantly).
// 256 threads = 256 experts. w double-buffered via the R11-VALIDATED 16B
// cp.async XOR-swizzle staging (full 256 rows x 32 floats per chunk); compute
// reads with the matching swizzled index (4-way conflict, hidden). Prefetch
// issued AFTER the chunk barrier (race-free double buffer). Per-expert FFMA
// chain: single accumulator, strictly ascending k — bitwise identical to the
// validated R7-R14 fixup.
// dyn smem: xs[2048] (8K) | ws[2][256*32] (64K) | sc[256] (1K) = 73 KB
// ---------------------------------------------------------------------------
#define WCH (256 * 32)
#define FIX_SMEM ((HDIM + 2 * WCH + NEXP) * 4)

__global__ __launch_bounds__(256) void fixup_kernel(
    const float* __restrict__ x, const float* __restrict__ w,
    const float* __restrict__ bias, float* __restrict__ out)
{
    if (blockIdx.x >= g_nflag) return;
    extern __shared__ float fsm[];
    float* xs = fsm;                 // HDIM
    float* ws = fsm + HDIM;          // 2*WCH
    float* sc = ws + 2 * WCH;        // NEXP
    const uint32_t ws_base = smem_u32(ws);
    const int tid = threadIdx.x;
    const int t = g_flaglist[blockIdx.x];

    // stage x token into smem (float4, coalesced)
    {
        const float4* src = (const float4*)(x + (size_t)t * HDIM);
        ((float4*)xs)[tid]       = src[tid];
        ((float4*)xs)[tid + 256] = src[tid + 256];
    }
    // w chunk 0: 16B cp.async, block-XOR swizzled dst (R11-validated pattern)
    #pragma unroll
    for (int i = 0; i < 8; i++) {
        int idx = tid + 256 * i;
        int er = idx >> 3, c4 = idx & 7;
        uint32_t dst = ws_base + (uint32_t)(er * 128 + ((c4 ^ (er & 7)) * 16));
        CP_ASYNC16(dst, w + (size_t)er * HDIM + c4 * 4);
    }
    CP_COMMIT();

    float acc = 0.0f;
    for (int kc = 0; kc < 64; kc++) {
        CP_WAIT(0);
        __syncthreads();
        if (kc + 1 < 64) {
            const uint32_t wb = ws_base + (uint32_t)((kc + 1) & 1) * (WCH * 4);
            #pragma unroll
            for (int i = 0; i < 8; i++) {
                int idx = tid + 256 * i;
                int er = idx >> 3, c4 = idx & 7;
                uint32_t dst = wb + (uint32_t)(er * 128 + ((c4 ^ (er & 7)) * 16));
                CP_ASYNC16(dst, w + (size_t)er * HDIM + (kc + 1) * 32 + c4 * 4);
            }
            CP_COMMIT();
        }
        const float* wbuf = ws + (kc & 1) * WCH;
        const float* xk = xs + kc * 32;
        #pragma unroll
        for (int k = 0; k < 32; k++) {
            float wv = wbuf[tid * 32 + (((k >> 2) ^ (tid & 7)) << 2) + (k & 3)];
            acc = fmaf(xk[k], wv, acc);   // ascending k, single accumulator
        }
    }
    sc[tid] = 1.0f / (1.0f + expf(-acc));
    __syncthreads();

    if (tid < 32) {
        const int lane = tid;
        float s[8], ch[8];
        #pragma unroll
        for (int j = 0; j < 8; j++) {
            s[j]  = sc[lane * 8 + j];
            ch[j] = s[j] + bias[lane * 8 + j];
        }
        float me, mg;
        route_core(s, ch, lane, t, out, false, &me, &mg);
    }
}

// ---------------------------------------------------------------------------
extern "C" void kernel_launch(void* const* d_in, const int* in_sizes, int n_in,
                              void* d_out, int out_size)
{
    const float* x    = (const float*)d_in[0];   // [4,4096,2048]
    const float* w    = (const float*)d_in[1];   // [256,2048]
    const float* bias = (const float*)d_in[2];   // [256]
    float* out = (float*)d_out;

    cudaFuncSetAttribute(gemm_mma_kernel,
                         cudaFuncAttributeMaxDynamicSharedMemorySize, SMEM_SZ);
    cudaFuncSetAttribute(fixup_kernel,
                         cudaFuncAttributeMaxDynamicSharedMemorySize, FIX_SMEM);

    split_b_kernel<<<(NEXP / 8) * (HDIM / 16) / 8, 256>>>(w);
    gemm_mma_kernel<<<T_TOKENS / 128, 256, SMEM_SZ>>>(x);
    route_kernel<<<T_TOKENS / 8, 256>>>(bias, out);
    fixup_kernel<<<2048, 256, FIX_SMEM>>>(x, w, bias, out);
}